// round 14
// baseline (speedup 1.0000x reference)
#include <cuda_runtime.h>
#include <math.h>
#include <stdint.h>

#define BB 64
#define SS 512
#define FF 128
#define HH 512
#define G4 2048
#define NCTA 128          // persist CTAs
#define NOUT 20           // out-role CTAs
#define NCTAG 32          // CTAs per b-group
#define TPB 512

// Scratch (static device globals — no allocation at kernel_launch time)
__device__ float g_hist[(size_t)SS * BB * HH];  // [S][B][H] h (tf32-rounded fp32)
__device__ unsigned g_cnt[4 * SS];              // per-(bgroup,step) counters

#define CP16(dst, src) asm volatile("cp.async.cg.shared.global [%0], [%1], 16;" \
                                    :: "r"(dst), "l"(src))

#define MMA_TF32(C, A, b0r, b1r) \
    asm volatile("mma.sync.aligned.m16n8k8.row.col.f32.tf32.tf32.f32 " \
        "{%0,%1,%2,%3}, {%4,%5,%6,%7}, {%8,%9}, {%0,%1,%2,%3};" \
        : "+f"(C[0]), "+f"(C[1]), "+f"(C[2]), "+f"(C[3]) \
        : "r"(A[0]), "r"(A[1]), "r"(A[2]), "r"(A[3]), "r"(b0r), "r"(b1r))

__device__ __forceinline__ unsigned f2tf32(float f) {
    unsigned u;
    asm("cvt.rna.tf32.f32 %0, %1;" : "=r"(u) : "f"(f));
    return u;
}

__global__ void init_kernel() {
    int i = blockIdx.x * blockDim.x + threadIdx.x;
    if (i < 4 * SS) g_cnt[i] = 0;
}

// ---------------------------------------------------------------------------
// Fused persistent kernel, grid = 148 CTAs.
//   blockIdx.x < 128 : LSTM persist (32 j-groups x 4 b-groups).
//     Per-warp register-resident tf32 fragments of BOTH W_hh (64 regs) and
//     W_ih (16 regs).  Per step: h tile via cp.async (16x512), inp tile
//     prefetched one step ahead (16x128, dependency-free), 32 h-mma +
//     8 xg-mma per warp into the same accumulators, partials to red SMEM,
//     owner warps add bias + reduce + gates.  No g_xg pass at all.
//   blockIdx.x >= 128: out-projection role (consumes per-step counters).
// SMEM (floats): hsu 16x516 | ins 2x16x132 | red 256x20 | bs 64
// ---------------------------------------------------------------------------
#define SM_HS   0
#define SM_INS  8256
#define SM_RED  12480
#define SM_BS   17600
#define SM_TOT  17664

__global__ __launch_bounds__(TPB, 1) void lstm_persist(
    const float* __restrict__ inp,  const float* __restrict__ Wih,
    const float* __restrict__ Whh,
    const float* __restrict__ bih,  const float* __restrict__ bhh,
    const float* __restrict__ Wout, const float* __restrict__ bout,
    float* __restrict__ out)
{
    extern __shared__ float sm[];
    const int t = threadIdx.x;

    if (blockIdx.x >= NCTA) {
        // ------------------- out-projection role -------------------
        float* As = sm;                 // [32][68]
        float* Bs = sm + 32 * 68;       // [32][68]
        const int o = blockIdx.x - NCTA;            // 0..19
        const int tx = t & 31, ty = t >> 5;         // f-pair, m-quad

        for (int tt = o; tt < 2 * SS; tt += NOUT) {
            const int s = tt >> 1;
            const int fBase = (tt & 1) << 6;

            // wait for all 4 b-groups of step s
            if (t < 4) {
                const unsigned* ca = g_cnt + t * SS + s;
                unsigned v;
                do {
                    asm volatile("ld.acquire.gpu.global.u32 %0, [%1];"
                                 : "=r"(v) : "l"(ca) : "memory");
                } while (v < NCTAG);
            }
            __syncthreads();

            float acc[4][2] = {};
            const float* hb = g_hist + ((size_t)s << 15);

            for (int k0 = 0; k0 < HH; k0 += 32) {
                {
                    int row = t >> 3, c4 = t & 7;
                    float4 v = *(const float4*)(hb + ((size_t)row << 9) + k0 + (c4 << 2));
                    As[(c4 * 4 + 0) * 68 + row] = v.x;
                    As[(c4 * 4 + 1) * 68 + row] = v.y;
                    As[(c4 * 4 + 2) * 68 + row] = v.z;
                    As[(c4 * 4 + 3) * 68 + row] = v.w;
                }
                {
                    int row = t >> 3, c4 = t & 7;
                    float4 v = *(const float4*)(Wout +
                        (size_t)(fBase + row) * HH + k0 + (c4 << 2));
                    Bs[(c4 * 4 + 0) * 68 + row] = v.x;
                    Bs[(c4 * 4 + 1) * 68 + row] = v.y;
                    Bs[(c4 * 4 + 2) * 68 + row] = v.z;
                    Bs[(c4 * 4 + 3) * 68 + row] = v.w;
                }
                __syncthreads();
                #pragma unroll
                for (int kk = 0; kk < 32; kk++) {
                    float a[4], b[2];
                    *(float4*)a = *(const float4*)&As[kk * 68 + ty * 4];
                    b[0] = Bs[kk * 68 + tx * 2];
                    b[1] = Bs[kk * 68 + tx * 2 + 1];
                    #pragma unroll
                    for (int i = 0; i < 4; i++) {
                        acc[i][0] += a[i] * b[0];
                        acc[i][1] += a[i] * b[1];
                    }
                }
                __syncthreads();
            }

            float bias0 = bout[fBase + tx * 2];
            float bias1 = bout[fBase + tx * 2 + 1];
            #pragma unroll
            for (int i = 0; i < 4; i++) {
                int b = ty * 4 + i;
                float2 ov;
                ov.x = acc[i][0] + bias0;
                ov.y = acc[i][1] + bias1;
                *(float2*)(out + ((size_t)b * SS + s) * FF + fBase + tx * 2) = ov;
            }
        }
        return;
    }

    // ---------------------- LSTM persist role ----------------------
    unsigned* hsu = (unsigned*)(sm + SM_HS);   // h tile, tf32 bits, pitch 516
    float* ins = sm + SM_INS;                  // inp tiles, 2 bufs, pitch 132
    float* red = sm + SM_RED;                  // [b*16+j][20]: kw*4+g
    float* bs  = sm + SM_BS;                   // bias [g*16+j]

    const int w = t >> 5, l = t & 31;
    const int kw = w >> 2, mw = w & 3;         // k-split, m-split
    const int gid = l >> 2, tig = l & 3;       // mma lane decode
    const int jgrp = blockIdx.x >> 2;
    const int bgrp = blockIdx.x & 3;
    const int jg0  = jgrp << 4;
    const int b0   = bgrp << 4;

    // Resident A fragments: W_hh (K slice kw*128) and W_ih (K slice kw*32)
    unsigned Af[16][4];
    unsigned Aih[4][4];
    {
        int m0 = (mw << 4) + gid;
        int m1 = m0 + 8;
        const float* r0 = Whh + (size_t)((m0 & 3) * HH + jg0 + (m0 >> 2)) * HH;
        const float* r1 = Whh + (size_t)((m1 & 3) * HH + jg0 + (m1 >> 2)) * HH;
        #pragma unroll
        for (int kt = 0; kt < 16; kt++) {
            int kc = (kw << 7) + (kt << 3) + tig;
            Af[kt][0] = f2tf32(__ldg(r0 + kc));
            Af[kt][1] = f2tf32(__ldg(r1 + kc));
            Af[kt][2] = f2tf32(__ldg(r0 + kc + 4));
            Af[kt][3] = f2tf32(__ldg(r1 + kc + 4));
        }
        const float* q0 = Wih + (size_t)((m0 & 3) * HH + jg0 + (m0 >> 2)) * FF;
        const float* q1 = Wih + (size_t)((m1 & 3) * HH + jg0 + (m1 >> 2)) * FF;
        #pragma unroll
        for (int kt = 0; kt < 4; kt++) {
            int kc = (kw << 5) + (kt << 3) + tig;
            Aih[kt][0] = f2tf32(__ldg(q0 + kc));
            Aih[kt][1] = f2tf32(__ldg(q1 + kc));
            Aih[kt][2] = f2tf32(__ldg(q0 + kc + 4));
            Aih[kt][3] = f2tf32(__ldg(q1 + kc + 4));
        }
    }

    // bias to SMEM: bs[g*16+j]
    if (t < 64) {
        int g = t >> 4, jo = t & 15;
        bs[t] = bih[g * HH + jg0 + jo] + bhh[g * HH + jg0 + jo];
    }

    // preload inp(0) tile: 16 batches x 128 k, one float4 per thread
    {
        int r = t >> 5, c4 = t & 31;
        uint32_t d = (uint32_t)__cvta_generic_to_shared(&ins[r * 132 + (c4 << 2)]);
        CP16(d, inp + ((size_t)(b0 + r) * SS + 0) * FF + (c4 << 2));
        asm volatile("cp.async.commit_group;");
        asm volatile("cp.async.wait_group 0;");
    }
    __syncthreads();

    float c = 0.f;

    for (int s = 0; s < SS; s++) {
        if (s > 0) {
            // h slice: all 16 warps, 16 batches x 32 k-cols each
            const float* hp = g_hist + ((size_t)(s - 1) << 15);
            #pragma unroll
            for (int it = 0; it < 4; it++) {
                int idx = (it << 5) + l;
                int r = idx >> 3, c8 = idx & 7;
                int col = (kw << 7) + (mw << 5) + (c8 << 2);
                uint32_t d = (uint32_t)__cvta_generic_to_shared(&hsu[r * 516 + col]);
                CP16(d, hp + ((size_t)(b0 + r) << 9) + col);
            }
            asm volatile("cp.async.commit_group;");
            asm volatile("cp.async.wait_group 0;");
            asm volatile("bar.sync %0, 128;" :: "r"(kw + 1));
        }

        // prefetch inp(s+1) during compute (dependency-free)
        if (s + 1 < SS) {
            int r = t >> 5, c4 = t & 31;
            uint32_t d = (uint32_t)__cvta_generic_to_shared(
                &ins[(((s + 1) & 1) * 2112) + r * 132 + (c4 << 2)]);
            CP16(d, inp + ((size_t)(b0 + r) * SS + (s + 1)) * FF + (c4 << 2));
            asm volatile("cp.async.commit_group;");
        }

        float C0[4] = {0.f, 0.f, 0.f, 0.f};
        float C1[4] = {0.f, 0.f, 0.f, 0.f};

        // xg mma: K slice kw*32 of inp tile
        {
            const unsigned* ib0 = (const unsigned*)ins + (s & 1) * 2112 +
                                  gid * 132 + (kw << 5) + tig;
            const unsigned* ib1 = ib0 + 8 * 132;
            #pragma unroll
            for (int kt = 0; kt < 4; kt++) {
                MMA_TF32(C0, Aih[kt], ib0[kt << 3], ib0[(kt << 3) + 4]);
                MMA_TF32(C1, Aih[kt], ib1[kt << 3], ib1[(kt << 3) + 4]);
            }
        }
        // h mma: K slice kw*128 of h tile
        if (s > 0) {
            const unsigned* hb0 = hsu + gid * 516 + (kw << 7) + tig;
            const unsigned* hb1 = hsu + (gid + 8) * 516 + (kw << 7) + tig;
            #pragma unroll
            for (int kt = 0; kt < 16; kt++) {
                unsigned b0r = hb0[kt << 3];
                unsigned b1r = hb0[(kt << 3) + 4];
                MMA_TF32(C0, Af[kt], b0r, b1r);
                unsigned b2r = hb1[kt << 3];
                unsigned b3r = hb1[(kt << 3) + 4];
                MMA_TF32(C1, Af[kt], b2r, b3r);
            }
        }

        // partials: red[(b*16+jl)*20 + kw*4+g]
        {
            const int jlA = (mw << 2) + (gid >> 2);
            const int gA  = gid & 3;
            const int bA  = tig << 1;
            const int cA  = (kw << 2) + gA;
            red[((bA)     * 16 + jlA)     * 20 + cA] = C0[0];
            red[((bA + 1) * 16 + jlA)     * 20 + cA] = C0[1];
            red[((bA)     * 16 + jlA + 2) * 20 + cA] = C0[2];
            red[((bA + 1) * 16 + jlA + 2) * 20 + cA] = C0[3];
            red[((bA + 8) * 16 + jlA)     * 20 + cA] = C1[0];
            red[((bA + 9) * 16 + jlA)     * 20 + cA] = C1[1];
            red[((bA + 8) * 16 + jlA + 2) * 20 + cA] = C1[2];
            red[((bA + 9) * 16 + jlA + 2) * 20 + cA] = C1[3];
        }
        __syncthreads();   // red ready; hsu/ins(s) reads complete

        if (t < 256) {
            // ---------------- owner phase (warps 0-7) ----------------
            const int jo = t & 15;
            const int bo = t >> 4;
            const float4* rp = (const float4*)(red + t * 20);
            float4 q0 = rp[0], q1 = rp[1], q2 = rp[2], q3 = rp[3];
            float a0 = bs[       jo] + q0.x + q1.x + q2.x + q3.x;
            float a1 = bs[16  +  jo] + q0.y + q1.y + q2.y + q3.y;
            float a2 = bs[32  +  jo] + q0.z + q1.z + q2.z + q3.z;
            float a3 = bs[48  +  jo] + q0.w + q1.w + q2.w + q3.w;
            float ig = 1.f / (1.f + __expf(-a0));
            float fg = 1.f / (1.f + __expf(-a1));
            float gg = 2.f / (1.f + __expf(-2.f * a2)) - 1.f;
            float og = 1.f / (1.f + __expf(-a3));
            c = fg * c + ig * gg;
            float th = 2.f / (1.f + __expf(-2.f * c)) - 1.f;
            float h = og * th;
            // store tf32-rounded h (bits valid as mma operand AND as fp32)
            g_hist[((size_t)(s * BB + b0 + bo) << 9) + jg0 + jo] =
                __uint_as_float(f2tf32(h));

            // owners-only barrier, then release this step's counter
            asm volatile("bar.sync 9, 256;");
            if (t == 0)
                asm volatile("red.release.gpu.global.add.u32 [%0], %1;"
                             :: "l"(g_cnt + bgrp * SS + s), "r"(1u) : "memory");
        } else if (t == 256) {
            // overlapped producer poll (lane 0 of warp 8)
            const unsigned* ca = g_cnt + bgrp * SS + s;
            unsigned v;
            do {
                asm volatile("ld.acquire.gpu.global.u32 %0, [%1];"
                             : "=r"(v) : "l"(ca) : "memory");
            } while (v < NCTAG);
        }
        __syncthreads();   // owners released + producers verified -> next step
    }
}

extern "C" void kernel_launch(void* const* d_in, const int* in_sizes, int n_in,
                              void* d_out, int out_size)
{
    const float* inp  = (const float*)d_in[0];
    const float* Wih  = (const float*)d_in[1];
    const float* Whh  = (const float*)d_in[2];
    const float* bih  = (const float*)d_in[3];
    const float* bhh  = (const float*)d_in[4];
    const float* Wout = (const float*)d_in[5];
    const float* bout = (const float*)d_in[6];
    float* out = (float*)d_out;

    const int smem_bytes = SM_TOT * 4;    // 70,656 B
    cudaFuncSetAttribute(lstm_persist,
                         cudaFuncAttributeMaxDynamicSharedMemorySize, smem_bytes);

    init_kernel<<<8, 256>>>();
    lstm_persist<<<NCTA + NOUT, TPB, smem_bytes>>>(
        inp, Wih, Whh, bih, bhh, Wout, bout, out);
}

// round 15
// speedup vs baseline: 1.3586x; 1.3586x over previous
#include <cuda_runtime.h>
#include <math.h>
#include <stdint.h>

#define BB 64
#define SS 512
#define FF 128
#define HH 512
#define G4 2048
#define NCTA 128          // persist CTAs
#define NOUT 20           // out-role CTAs
#define NCTAG 32          // CTAs per b-group
#define TPB 512

// Scratch (static device globals — no allocation at kernel_launch time)
__device__ float g_xg[(size_t)SS * BB * G4];    // [S][B][4H] input gates
__device__ float g_hist[(size_t)SS * BB * HH];  // [S][B][H] h (tf32-rounded fp32)
__device__ unsigned g_cnt[4 * SS];              // per-(bgroup,step) counters

#define CP16(dst, src) asm volatile("cp.async.cg.shared.global [%0], [%1], 16;" \
                                    :: "r"(dst), "l"(src))

#define MMA_TF32(C, A, b0r, b1r) \
    asm volatile("mma.sync.aligned.m16n8k8.row.col.f32.tf32.tf32.f32 " \
        "{%0,%1,%2,%3}, {%4,%5,%6,%7}, {%8,%9}, {%0,%1,%2,%3};" \
        : "+f"(C[0]), "+f"(C[1]), "+f"(C[2]), "+f"(C[3]) \
        : "r"(A[0]), "r"(A[1]), "r"(A[2]), "r"(A[3]), "r"(b0r), "r"(b1r))

__device__ __forceinline__ unsigned f2tf32(float f) {
    unsigned u;
    asm("cvt.rna.tf32.f32 %0, %1;" : "=r"(u) : "f"(f));
    return u;
}

__global__ void init_kernel() {
    int i = blockIdx.x * blockDim.x + threadIdx.x;
    if (i < 4 * SS) g_cnt[i] = 0;
}

// ---------------------------------------------------------------------------
// x_gates GEMM on tensor cores (tf32), DOUBLE-BUFFERED subtile pipeline.
// C[g][m] = sum_f Wih[g,f]*inp[m,f];  g_xg[m][g] = C + bias.
// Grid (32 g-groups, 64 m-chunks).  CTA: 64 g x 512 m, 8 subtiles of 64 m.
// 8 warps = aw(4 g-tiles of 16) x nh(2 n-halves of 32).  A frags resident.
// While computing subtile s, subtile s+1's 8 KB inp load is in flight.
// SMEM floats: hsx 2x(64x132) | cs 64x68 | bs 64
// ---------------------------------------------------------------------------
#define XG_HS  0
#define XG_CS  16896
#define XG_BS  21248
#define XG_TOT 21312

__global__ __launch_bounds__(256) void xg_tc(
    const float* __restrict__ inp, const float* __restrict__ Wih,
    const float* __restrict__ bih, const float* __restrict__ bhh)
{
    extern __shared__ float sx[];
    float* hsx = sx + XG_HS;     // two 8448-float buffers
    float* cs  = sx + XG_CS;
    float* bs  = sx + XG_BS;

    const int t = threadIdx.x;
    const int w = t >> 5, l = t & 31;
    const int gid = l >> 2, tig = l & 3;
    const int aw = w >> 1, nh = w & 1;
    const int gBase = blockIdx.x << 6;

    if (t < 64) bs[t] = bih[gBase + t] + bhh[gBase + t];

    // Resident A fragments: W rows m0,m1 of this warp's g-tile
    unsigned Af[16][4];
    {
        const int m0 = (aw << 4) + gid;
        const float* r0 = Wih + (size_t)(gBase + m0) * FF;
        const float* r1 = Wih + (size_t)(gBase + m0 + 8) * FF;
        #pragma unroll
        for (int kt = 0; kt < 16; kt++) {
            int kc = (kt << 3) + tig;
            Af[kt][0] = f2tf32(__ldg(r0 + kc));
            Af[kt][1] = f2tf32(__ldg(r1 + kc));
            Af[kt][2] = f2tf32(__ldg(r0 + kc + 4));
            Af[kt][3] = f2tf32(__ldg(r1 + kc + 4));
        }
    }

    // preload subtile 0 into buffer 0
    {
        const int sfix = (blockIdx.y << 3);
        #pragma unroll
        for (int it = 0; it < 8; it++) {
            int idx = t + (it << 8);
            int r = idx >> 5, c4 = idx & 31;
            uint32_t d = (uint32_t)__cvta_generic_to_shared(&hsx[r * 132 + (c4 << 2)]);
            CP16(d, inp + ((size_t)r * SS + sfix) * FF + (c4 << 2));
        }
        asm volatile("cp.async.commit_group;");
    }

    for (int sub = 0; sub < 8; sub++) {
        const int sfix = (blockIdx.y << 3) + sub;

        // issue next subtile's load into the other buffer
        if (sub < 7) {
            float* dstb = hsx + (((sub + 1) & 1) * 8448);
            #pragma unroll
            for (int it = 0; it < 8; it++) {
                int idx = t + (it << 8);
                int r = idx >> 5, c4 = idx & 31;
                uint32_t d = (uint32_t)__cvta_generic_to_shared(
                    &dstb[r * 132 + (c4 << 2)]);
                CP16(d, inp + ((size_t)r * SS + sfix + 1) * FF + (c4 << 2));
            }
            asm volatile("cp.async.commit_group;");
            asm volatile("cp.async.wait_group 1;");
        } else {
            asm volatile("cp.async.wait_group 0;");
        }
        __syncthreads();

        const float* buf = hsx + ((sub & 1) * 8448);

        float C[4][4] = {};
        #pragma unroll
        for (int nt = 0; nt < 4; nt++) {
            const unsigned* hb = (const unsigned*)buf +
                (((nh << 5) + (nt << 3) + gid) * 132 + tig);
            #pragma unroll
            for (int kt = 0; kt < 16; kt++) {
                unsigned b0r = hb[kt << 3];
                unsigned b1r = hb[(kt << 3) + 4];
                MMA_TF32(C[nt], Af[kt], b0r, b1r);
            }
        }

        // stage C -> cs[mrow][g]
        const int grow = (aw << 4) + gid;
        #pragma unroll
        for (int nt = 0; nt < 4; nt++) {
            int base = (nh << 5) + (nt << 3) + (tig << 1);
            cs[ base      * 68 + grow    ] = C[nt][0];
            cs[(base + 1) * 68 + grow    ] = C[nt][1];
            cs[ base      * 68 + grow + 8] = C[nt][2];
            cs[(base + 1) * 68 + grow + 8] = C[nt][3];
        }
        __syncthreads();

        // coalesced store with bias: 64 rows x 64 g
        #pragma unroll
        for (int it = 0; it < 4; it++) {
            int idx = t + (it << 8);
            int row = idx >> 4, c4 = idx & 15;
            float4 v = *(const float4*)&cs[row * 68 + (c4 << 2)];
            float4 bb = *(const float4*)&bs[c4 << 2];
            v.x += bb.x; v.y += bb.y; v.z += bb.z; v.w += bb.w;
            *(float4*)(g_xg + (size_t)((sfix << 6) + row) * G4 + gBase + (c4 << 2)) = v;
        }
        __syncthreads();
    }
}

// ---------------------------------------------------------------------------
// Fused persistent kernel, grid = 148 CTAs (R11, unchanged).
// Sync: per-b-group counter, red.release.gpu.add by t0 after owners' bar9;
// single poller (t==256) overlapped with the owner phase.
// SMEM (floats): hs 16x516 | xg2 2x1024 | red 256x20
// ---------------------------------------------------------------------------
#define SM_HS   0
#define SM_XG   8256
#define SM_RED  10304
#define SM_TOT  15424

__global__ __launch_bounds__(TPB, 1) void lstm_persist(
    const float* __restrict__ Whh, const float* __restrict__ Wout,
    const float* __restrict__ bout, float* __restrict__ out)
{
    extern __shared__ float sm[];
    const int t = threadIdx.x;

    if (blockIdx.x >= NCTA) {
        // ------------------- out-projection role -------------------
        float* As = sm;                 // [32][68]
        float* Bs = sm + 32 * 68;       // [32][68]
        const int o = blockIdx.x - NCTA;            // 0..19
        const int tx = t & 31, ty = t >> 5;         // f-pair, m-quad

        for (int tt = o; tt < 2 * SS; tt += NOUT) {
            const int s = tt >> 1;
            const int fBase = (tt & 1) << 6;

            // wait for all 4 b-groups of step s
            if (t < 4) {
                const unsigned* ca = g_cnt + t * SS + s;
                unsigned v;
                do {
                    asm volatile("ld.acquire.gpu.global.u32 %0, [%1];"
                                 : "=r"(v) : "l"(ca) : "memory");
                } while (v < NCTAG);
            }
            __syncthreads();

            float acc[4][2] = {};
            const float* hb = g_hist + ((size_t)s << 15);

            for (int k0 = 0; k0 < HH; k0 += 32) {
                {
                    int row = t >> 3, c4 = t & 7;
                    float4 v = *(const float4*)(hb + ((size_t)row << 9) + k0 + (c4 << 2));
                    As[(c4 * 4 + 0) * 68 + row] = v.x;
                    As[(c4 * 4 + 1) * 68 + row] = v.y;
                    As[(c4 * 4 + 2) * 68 + row] = v.z;
                    As[(c4 * 4 + 3) * 68 + row] = v.w;
                }
                {
                    int row = t >> 3, c4 = t & 7;
                    float4 v = *(const float4*)(Wout +
                        (size_t)(fBase + row) * HH + k0 + (c4 << 2));
                    Bs[(c4 * 4 + 0) * 68 + row] = v.x;
                    Bs[(c4 * 4 + 1) * 68 + row] = v.y;
                    Bs[(c4 * 4 + 2) * 68 + row] = v.z;
                    Bs[(c4 * 4 + 3) * 68 + row] = v.w;
                }
                __syncthreads();
                #pragma unroll
                for (int kk = 0; kk < 32; kk++) {
                    float a[4], b[2];
                    *(float4*)a = *(const float4*)&As[kk * 68 + ty * 4];
                    b[0] = Bs[kk * 68 + tx * 2];
                    b[1] = Bs[kk * 68 + tx * 2 + 1];
                    #pragma unroll
                    for (int i = 0; i < 4; i++) {
                        acc[i][0] += a[i] * b[0];
                        acc[i][1] += a[i] * b[1];
                    }
                }
                __syncthreads();
            }

            float bias0 = bout[fBase + tx * 2];
            float bias1 = bout[fBase + tx * 2 + 1];
            #pragma unroll
            for (int i = 0; i < 4; i++) {
                int b = ty * 4 + i;
                float2 ov;
                ov.x = acc[i][0] + bias0;
                ov.y = acc[i][1] + bias1;
                *(float2*)(out + ((size_t)b * SS + s) * FF + fBase + tx * 2) = ov;
            }
        }
        return;
    }

    // ---------------------- LSTM persist role ----------------------
    unsigned* hsu = (unsigned*)(sm + SM_HS);   // h tile, tf32 bits, pitch 516
    float* xg2 = sm + SM_XG;
    float* red = sm + SM_RED;                  // [b*16+j][20]: kw*4+g

    const int w = t >> 5, l = t & 31;
    const int kw = w >> 2, mw = w & 3;         // k-split, m-split
    const int gid = l >> 2, tig = l & 3;       // mma lane decode
    const int jgrp = blockIdx.x >> 2;
    const int bgrp = blockIdx.x & 3;
    const int jg0  = jgrp << 4;
    const int b0   = bgrp << 4;

    // Resident A fragments (W_hh rows, rna tf32)
    unsigned Af[16][4];
    {
        int m0 = (mw << 4) + gid;
        int m1 = m0 + 8;
        const float* r0 = Whh + (size_t)((m0 & 3) * HH + jg0 + (m0 >> 2)) * HH;
        const float* r1 = Whh + (size_t)((m1 & 3) * HH + jg0 + (m1 >> 2)) * HH;
        #pragma unroll
        for (int kt = 0; kt < 16; kt++) {
            int kc = (kw << 7) + (kt << 3) + tig;
            Af[kt][0] = f2tf32(__ldg(r0 + kc));
            Af[kt][1] = f2tf32(__ldg(r1 + kc));
            Af[kt][2] = f2tf32(__ldg(r0 + kc + 4));
            Af[kt][3] = f2tf32(__ldg(r1 + kc + 4));
        }
    }

    // Prefetch xg(0) and xg(1) (warps 0-7), separate commit groups
    if (t < 256) {
        int bi = t >> 4, cc = t & 15;
        int g = cc >> 2, j4 = cc & 3;
        {
            const float* src = g_xg + (size_t)(b0 + bi) * G4 + g * HH + jg0 + (j4 << 2);
            uint32_t d = (uint32_t)__cvta_generic_to_shared(
                &xg2[((g << 4) + bi) * 16 + (j4 << 2)]);
            CP16(d, src);
            asm volatile("cp.async.commit_group;");
        }
        {
            const float* src = g_xg + (size_t)(BB + b0 + bi) * G4 + g * HH + jg0 + (j4 << 2);
            uint32_t d = (uint32_t)__cvta_generic_to_shared(
                &xg2[1024 + ((g << 4) + bi) * 16 + (j4 << 2)]);
            CP16(d, src);
            asm volatile("cp.async.commit_group;");
        }
    }
    __syncthreads();

    float c = 0.f;

    for (int s = 0; s < SS; s++) {
        if (s > 0) {
            // h slice (tf32 bits straight from g_hist); producers for step
            // s-1 were verified by warp 8's poll last iteration.
            {
                const float* hp = g_hist + ((size_t)(s - 1) << 15);
                #pragma unroll
                for (int it = 0; it < 4; it++) {
                    int idx = (it << 5) + l;
                    int r = idx >> 3, c8 = idx & 7;
                    int col = (kw << 7) + (mw << 5) + (c8 << 2);
                    uint32_t d = (uint32_t)__cvta_generic_to_shared(
                        &hsu[r * 516 + col]);
                    CP16(d, hp + ((size_t)(b0 + r) << 9) + col);
                }
                asm volatile("cp.async.commit_group;");
                asm volatile("cp.async.wait_group 0;");
                asm volatile("bar.sync %0, 128;" :: "r"(kw + 1));
            }

            // Prefetch xg(s+1) during compute (warps 0-7 only)
            if (t < 256 && s + 1 < SS) {
                int bi = t >> 4, cc = t & 15;
                int g = cc >> 2, j4 = cc & 3;
                const float* src = g_xg +
                    (size_t)((s + 1) * BB + b0 + bi) * G4 + g * HH + jg0 + (j4 << 2);
                uint32_t d = (uint32_t)__cvta_generic_to_shared(
                    &xg2[(((s + 1) & 1) << 10) + ((g << 4) + bi) * 16 + (j4 << 2)]);
                CP16(d, src);
                asm volatile("cp.async.commit_group;");
            }

            float C0[4] = {0.f, 0.f, 0.f, 0.f};
            float C1[4] = {0.f, 0.f, 0.f, 0.f};
            const unsigned* hb0 = hsu + gid * 516 + (kw << 7) + tig;
            const unsigned* hb1 = hsu + (gid + 8) * 516 + (kw << 7) + tig;
            #pragma unroll
            for (int kt = 0; kt < 16; kt++) {
                unsigned b0r = hb0[kt << 3];
                unsigned b1r = hb0[(kt << 3) + 4];
                MMA_TF32(C0, Af[kt], b0r, b1r);
                unsigned b2r = hb1[kt << 3];
                unsigned b3r = hb1[(kt << 3) + 4];
                MMA_TF32(C1, Af[kt], b2r, b3r);
            }

            // partials: red[(b*16+jl)*20 + kw*4+g]
            {
                const int jlA = (mw << 2) + (gid >> 2);
                const int gA  = gid & 3;
                const int bA  = tig << 1;
                const int cA  = (kw << 2) + gA;
                red[((bA)     * 16 + jlA)     * 20 + cA] = C0[0];
                red[((bA + 1) * 16 + jlA)     * 20 + cA] = C0[1];
                red[((bA)     * 16 + jlA + 2) * 20 + cA] = C0[2];
                red[((bA + 1) * 16 + jlA + 2) * 20 + cA] = C0[3];
                red[((bA + 8) * 16 + jlA)     * 20 + cA] = C1[0];
                red[((bA + 9) * 16 + jlA)     * 20 + cA] = C1[1];
                red[((bA + 8) * 16 + jlA + 2) * 20 + cA] = C1[2];
                red[((bA + 9) * 16 + jlA + 2) * 20 + cA] = C1[3];
            }
        } else {
            // xg(0) must be resident (xg(1) may still be in flight)
            if (t < 256) asm volatile("cp.async.wait_group 1;");
        }
        __syncthreads();   // red ready; hs reads complete

        if (t < 256) {
            // ---------------- owner phase (warps 0-7) ----------------
            const int jo = t & 15, bo = t >> 4;
            const float* xb = xg2 + ((s & 1) << 10);
            float a0 = xb[       (bo << 4) + jo];
            float a1 = xb[256 +  (bo << 4) + jo];
            float a2 = xb[512 +  (bo << 4) + jo];
            float a3 = xb[768 +  (bo << 4) + jo];
            if (s > 0) {
                const float4* rp = (const float4*)(red + t * 20);
                float4 q0 = rp[0], q1 = rp[1], q2 = rp[2], q3 = rp[3];
                a0 += q0.x + q1.x + q2.x + q3.x;
                a1 += q0.y + q1.y + q2.y + q3.y;
                a2 += q0.z + q1.z + q2.z + q3.z;
                a3 += q0.w + q1.w + q2.w + q3.w;
            }
            float ig = 1.f / (1.f + __expf(-a0));
            float fg = 1.f / (1.f + __expf(-a1));
            float gg = 2.f / (1.f + __expf(-2.f * a2)) - 1.f;
            float og = 1.f / (1.f + __expf(-a3));
            c = fg * c + ig * gg;
            float th = 2.f / (1.f + __expf(-2.f * c)) - 1.f;
            float h = og * th;
            // store tf32-rounded h (bits valid as mma operand AND as fp32)
            g_hist[((size_t)(s * BB + b0 + bo) << 9) + jg0 + jo] =
                __uint_as_float(f2tf32(h));

            // owners-only barrier, then release this step's counter
            asm volatile("bar.sync 9, 256;");
            if (t == 0)
                asm volatile("red.release.gpu.global.add.u32 [%0], %1;"
                             :: "l"(g_cnt + bgrp * SS + s), "r"(1u) : "memory");
        } else if (t == 256) {
            // overlapped producer poll (lane 0 of warp 8)
            const unsigned* ca = g_cnt + bgrp * SS + s;
            unsigned v;
            do {
                asm volatile("ld.acquire.gpu.global.u32 %0, [%1];"
                             : "=r"(v) : "l"(ca) : "memory");
            } while (v < NCTAG);
        }
        __syncthreads();   // owners released + producers verified -> next step
    }
}

extern "C" void kernel_launch(void* const* d_in, const int* in_sizes, int n_in,
                              void* d_out, int out_size)
{
    const float* inp  = (const float*)d_in[0];
    const float* Wih  = (const float*)d_in[1];
    const float* Whh  = (const float*)d_in[2];
    const float* bih  = (const float*)d_in[3];
    const float* bhh  = (const float*)d_in[4];
    const float* Wout = (const float*)d_in[5];
    const float* bout = (const float*)d_in[6];
    float* out = (float*)d_out;

    const int smem_bytes = SM_TOT * 4;    // 61,696 B
    const int xg_bytes   = XG_TOT * 4;    // 85,248 B
    cudaFuncSetAttribute(lstm_persist,
                         cudaFuncAttributeMaxDynamicSharedMemorySize, smem_bytes);
    cudaFuncSetAttribute(xg_tc,
                         cudaFuncAttributeMaxDynamicSharedMemorySize, xg_bytes);

    init_kernel<<<8, 256>>>();
    xg_tc<<<dim3(G4 / 64, 64), 256, xg_bytes>>>(inp, Wih, bih, bhh);
    lstm_persist<<<NCTA + NOUT, TPB, smem_bytes>>>(Whh, Wout, bout, out);
}

// round 16
// speedup vs baseline: 1.5214x; 1.1199x over previous
#include <cuda_runtime.h>
#include <cuda_fp16.h>
#include <math.h>
#include <stdint.h>

#define BB 64
#define SS 512
#define FF 128
#define HH 512
#define G4 2048
#define NCTA 128          // persist CTAs
#define NOUT 20           // out-role CTAs
#define NCTAG 32          // CTAs per b-group
#define TPB 512

// Scratch (static device globals — no allocation at kernel_launch time)
__device__ float g_xg[(size_t)SS * BB * G4];      // [S][B][4H] input gates
__device__ __half g_hist16[(size_t)SS * BB * HH]; // [S][B][H] h in fp16
__device__ unsigned g_cnt[4 * SS];                // per-(bgroup,step) counters

#define CP16(dst, src) asm volatile("cp.async.cg.shared.global [%0], [%1], 16;" \
                                    :: "r"(dst), "l"(src))

#define MMA_TF32(C, A, b0r, b1r) \
    asm volatile("mma.sync.aligned.m16n8k8.row.col.f32.tf32.tf32.f32 " \
        "{%0,%1,%2,%3}, {%4,%5,%6,%7}, {%8,%9}, {%0,%1,%2,%3};" \
        : "+f"(C[0]), "+f"(C[1]), "+f"(C[2]), "+f"(C[3]) \
        : "r"(A[0]), "r"(A[1]), "r"(A[2]), "r"(A[3]), "r"(b0r), "r"(b1r))

#define MMA_F16(C, A, b0r, b1r) \
    asm volatile("mma.sync.aligned.m16n8k16.row.col.f32.f16.f16.f32 " \
        "{%0,%1,%2,%3}, {%4,%5,%6,%7}, {%8,%9}, {%0,%1,%2,%3};" \
        : "+f"(C[0]), "+f"(C[1]), "+f"(C[2]), "+f"(C[3]) \
        : "r"(A[0]), "r"(A[1]), "r"(A[2]), "r"(A[3]), "r"(b0r), "r"(b1r))

__device__ __forceinline__ unsigned f2tf32(float f) {
    unsigned u;
    asm("cvt.rna.tf32.f32 %0, %1;" : "=r"(u) : "f"(f));
    return u;
}

__device__ __forceinline__ unsigned packh2(float x, float y) {
    __half2 h = __floats2half2_rn(x, y);
    return *(unsigned*)&h;
}

__global__ void init_kernel() {
    int i = blockIdx.x * blockDim.x + threadIdx.x;
    if (i < 4 * SS) g_cnt[i] = 0;
}

// ---------------------------------------------------------------------------
// x_gates GEMM on tensor cores (tf32), double-buffered subtile pipeline (R15).
// SMEM floats: hsx 2x(64x132) | cs 64x68 | bs 64
// ---------------------------------------------------------------------------
#define XG_HS  0
#define XG_CS  16896
#define XG_BS  21248
#define XG_TOT 21312

__global__ __launch_bounds__(256) void xg_tc(
    const float* __restrict__ inp, const float* __restrict__ Wih,
    const float* __restrict__ bih, const float* __restrict__ bhh)
{
    extern __shared__ float sx[];
    float* hsx = sx + XG_HS;     // two 8448-float buffers
    float* cs  = sx + XG_CS;
    float* bs  = sx + XG_BS;

    const int t = threadIdx.x;
    const int w = t >> 5, l = t & 31;
    const int gid = l >> 2, tig = l & 3;
    const int aw = w >> 1, nh = w & 1;
    const int gBase = blockIdx.x << 6;

    if (t < 64) bs[t] = bih[gBase + t] + bhh[gBase + t];

    unsigned Af[16][4];
    {
        const int m0 = (aw << 4) + gid;
        const float* r0 = Wih + (size_t)(gBase + m0) * FF;
        const float* r1 = Wih + (size_t)(gBase + m0 + 8) * FF;
        #pragma unroll
        for (int kt = 0; kt < 16; kt++) {
            int kc = (kt << 3) + tig;
            Af[kt][0] = f2tf32(__ldg(r0 + kc));
            Af[kt][1] = f2tf32(__ldg(r1 + kc));
            Af[kt][2] = f2tf32(__ldg(r0 + kc + 4));
            Af[kt][3] = f2tf32(__ldg(r1 + kc + 4));
        }
    }

    // preload subtile 0 into buffer 0
    {
        const int sfix = (blockIdx.y << 3);
        #pragma unroll
        for (int it = 0; it < 8; it++) {
            int idx = t + (it << 8);
            int r = idx >> 5, c4 = idx & 31;
            uint32_t d = (uint32_t)__cvta_generic_to_shared(&hsx[r * 132 + (c4 << 2)]);
            CP16(d, inp + ((size_t)r * SS + sfix) * FF + (c4 << 2));
        }
        asm volatile("cp.async.commit_group;");
    }

    for (int sub = 0; sub < 8; sub++) {
        const int sfix = (blockIdx.y << 3) + sub;

        if (sub < 7) {
            float* dstb = hsx + (((sub + 1) & 1) * 8448);
            #pragma unroll
            for (int it = 0; it < 8; it++) {
                int idx = t + (it << 8);
                int r = idx >> 5, c4 = idx & 31;
                uint32_t d = (uint32_t)__cvta_generic_to_shared(
                    &dstb[r * 132 + (c4 << 2)]);
                CP16(d, inp + ((size_t)r * SS + sfix + 1) * FF + (c4 << 2));
            }
            asm volatile("cp.async.commit_group;");
            asm volatile("cp.async.wait_group 1;");
        } else {
            asm volatile("cp.async.wait_group 0;");
        }
        __syncthreads();

        const float* buf = hsx + ((sub & 1) * 8448);

        float C[4][4] = {};
        #pragma unroll
        for (int nt = 0; nt < 4; nt++) {
            const unsigned* hb = (const unsigned*)buf +
                (((nh << 5) + (nt << 3) + gid) * 132 + tig);
            #pragma unroll
            for (int kt = 0; kt < 16; kt++) {
                unsigned b0r = hb[kt << 3];
                unsigned b1r = hb[(kt << 3) + 4];
                MMA_TF32(C[nt], Af[kt], b0r, b1r);
            }
        }

        const int grow = (aw << 4) + gid;
        #pragma unroll
        for (int nt = 0; nt < 4; nt++) {
            int base = (nh << 5) + (nt << 3) + (tig << 1);
            cs[ base      * 68 + grow    ] = C[nt][0];
            cs[(base + 1) * 68 + grow    ] = C[nt][1];
            cs[ base      * 68 + grow + 8] = C[nt][2];
            cs[(base + 1) * 68 + grow + 8] = C[nt][3];
        }
        __syncthreads();

        #pragma unroll
        for (int it = 0; it < 4; it++) {
            int idx = t + (it << 8);
            int row = idx >> 4, c4 = idx & 15;
            float4 v = *(const float4*)&cs[row * 68 + (c4 << 2)];
            float4 bb = *(const float4*)&bs[c4 << 2];
            v.x += bb.x; v.y += bb.y; v.z += bb.z; v.w += bb.w;
            *(float4*)(g_xg + (size_t)((sfix << 6) + row) * G4 + gBase + (c4 << 2)) = v;
        }
        __syncthreads();
    }
}

// ---------------------------------------------------------------------------
// Fused persistent kernel, grid = 148 CTAs (R11 structure).
// Recurrent GEMM now fp16 m16n8k16 (fp32 accum): h stored fp16 in g_hist16,
// W_hh fragments resident fp16, half the L2 broadcast traffic + half the mma.
// SMEM (floats): hsu16 16x520 halves (4160 f) | xg2 2x1024 | red 256x20
// ---------------------------------------------------------------------------
#define SM_XG   4160
#define SM_RED  6208
#define SM_TOT  11328

__global__ __launch_bounds__(TPB, 1) void lstm_persist(
    const float* __restrict__ Whh, const float* __restrict__ Wout,
    const float* __restrict__ bout, float* __restrict__ out)
{
    extern __shared__ float sm[];
    const int t = threadIdx.x;

    if (blockIdx.x >= NCTA) {
        // ------------------- out-projection role -------------------
        float* As = sm;                 // [32][68]
        float* Bs = sm + 32 * 68;       // [32][68]
        const int o = blockIdx.x - NCTA;            // 0..19
        const int tx = t & 31, ty = t >> 5;         // f-pair, m-quad

        for (int tt = o; tt < 2 * SS; tt += NOUT) {
            const int s = tt >> 1;
            const int fBase = (tt & 1) << 6;

            // wait for all 4 b-groups of step s
            if (t < 4) {
                const unsigned* ca = g_cnt + t * SS + s;
                unsigned v;
                do {
                    asm volatile("ld.acquire.gpu.global.u32 %0, [%1];"
                                 : "=r"(v) : "l"(ca) : "memory");
                } while (v < NCTAG);
            }
            __syncthreads();

            float acc[4][2] = {};
            const __half* hb16 = g_hist16 + ((size_t)s << 15);

            for (int k0 = 0; k0 < HH; k0 += 32) {
                {   // h tile (fp16 -> fp32): 64 rows x 32 k
                    int row = t >> 3, c4 = t & 7;
                    const __half* src = hb16 + ((size_t)row << 9) + k0 + (c4 << 2);
                    __half2 p0 = *(const __half2*)(src);
                    __half2 p1 = *(const __half2*)(src + 2);
                    float2 f0 = __half22float2(p0);
                    float2 f1 = __half22float2(p1);
                    As[(c4 * 4 + 0) * 68 + row] = f0.x;
                    As[(c4 * 4 + 1) * 68 + row] = f0.y;
                    As[(c4 * 4 + 2) * 68 + row] = f1.x;
                    As[(c4 * 4 + 3) * 68 + row] = f1.y;
                }
                {
                    int row = t >> 3, c4 = t & 7;
                    float4 v = *(const float4*)(Wout +
                        (size_t)(fBase + row) * HH + k0 + (c4 << 2));
                    Bs[(c4 * 4 + 0) * 68 + row] = v.x;
                    Bs[(c4 * 4 + 1) * 68 + row] = v.y;
                    Bs[(c4 * 4 + 2) * 68 + row] = v.z;
                    Bs[(c4 * 4 + 3) * 68 + row] = v.w;
                }
                __syncthreads();
                #pragma unroll
                for (int kk = 0; kk < 32; kk++) {
                    float a[4], b[2];
                    *(float4*)a = *(const float4*)&As[kk * 68 + ty * 4];
                    b[0] = Bs[kk * 68 + tx * 2];
                    b[1] = Bs[kk * 68 + tx * 2 + 1];
                    #pragma unroll
                    for (int i = 0; i < 4; i++) {
                        acc[i][0] += a[i] * b[0];
                        acc[i][1] += a[i] * b[1];
                    }
                }
                __syncthreads();
            }

            float bias0 = bout[fBase + tx * 2];
            float bias1 = bout[fBase + tx * 2 + 1];
            #pragma unroll
            for (int i = 0; i < 4; i++) {
                int b = ty * 4 + i;
                float2 ov;
                ov.x = acc[i][0] + bias0;
                ov.y = acc[i][1] + bias1;
                *(float2*)(out + ((size_t)b * SS + s) * FF + fBase + tx * 2) = ov;
            }
        }
        return;
    }

    // ---------------------- LSTM persist role ----------------------
    __half* hsu16 = (__half*)sm;               // h tile fp16, pitch 520 halves
    float* xg2 = sm + SM_XG;
    float* red = sm + SM_RED;                  // [b*16+j][20]: kw*4+g

    const int w = t >> 5, l = t & 31;
    const int kw = w >> 2, mw = w & 3;         // k-split, m-split
    const int gid = l >> 2, tig = l & 3;       // mma lane decode
    const int jgrp = blockIdx.x >> 2;
    const int bgrp = blockIdx.x & 3;
    const int jg0  = jgrp << 4;
    const int b0   = bgrp << 4;

    // Resident A fragments (W_hh rows, fp16 pairs) — m16n8k16 layout
    unsigned Ah[8][4];
    {
        int m0 = (mw << 4) + gid;
        int m1 = m0 + 8;
        const float* r0 = Whh + (size_t)((m0 & 3) * HH + jg0 + (m0 >> 2)) * HH;
        const float* r1 = Whh + (size_t)((m1 & 3) * HH + jg0 + (m1 >> 2)) * HH;
        #pragma unroll
        for (int kt = 0; kt < 8; kt++) {
            int kc = (kw << 7) + (kt << 4) + (tig << 1);
            Ah[kt][0] = packh2(__ldg(r0 + kc),     __ldg(r0 + kc + 1));
            Ah[kt][1] = packh2(__ldg(r1 + kc),     __ldg(r1 + kc + 1));
            Ah[kt][2] = packh2(__ldg(r0 + kc + 8), __ldg(r0 + kc + 9));
            Ah[kt][3] = packh2(__ldg(r1 + kc + 8), __ldg(r1 + kc + 9));
        }
    }

    // Prefetch xg(0) and xg(1) (warps 0-7), separate commit groups
    if (t < 256) {
        int bi = t >> 4, cc = t & 15;
        int g = cc >> 2, j4 = cc & 3;
        {
            const float* src = g_xg + (size_t)(b0 + bi) * G4 + g * HH + jg0 + (j4 << 2);
            uint32_t d = (uint32_t)__cvta_generic_to_shared(
                &xg2[((g << 4) + bi) * 16 + (j4 << 2)]);
            CP16(d, src);
            asm volatile("cp.async.commit_group;");
        }
        {
            const float* src = g_xg + (size_t)(BB + b0 + bi) * G4 + g * HH + jg0 + (j4 << 2);
            uint32_t d = (uint32_t)__cvta_generic_to_shared(
                &xg2[1024 + ((g << 4) + bi) * 16 + (j4 << 2)]);
            CP16(d, src);
            asm volatile("cp.async.commit_group;");
        }
    }
    __syncthreads();

    float c = 0.f;

    for (int s = 0; s < SS; s++) {
        if (s > 0) {
            // h slice (fp16): warp (kw,mw) loads 16 rows x 32 halves (1 KB)
            {
                const __half* hp16 = g_hist16 + ((size_t)(s - 1) << 15);
                #pragma unroll
                for (int it = 0; it < 2; it++) {
                    int idx = (it << 5) + l;
                    int r = idx >> 2, cc8 = idx & 3;
                    int col = (kw << 7) + (mw << 5) + (cc8 << 3);
                    uint32_t d = (uint32_t)__cvta_generic_to_shared(
                        &hsu16[r * 520 + col]);
                    CP16(d, hp16 + ((size_t)(b0 + r) << 9) + col);
                }
                asm volatile("cp.async.commit_group;");
                asm volatile("cp.async.wait_group 0;");
                asm volatile("bar.sync %0, 128;" :: "r"(kw + 1));
            }

            // Prefetch xg(s+1) during compute (warps 0-7 only)
            if (t < 256 && s + 1 < SS) {
                int bi = t >> 4, cc = t & 15;
                int g = cc >> 2, j4 = cc & 3;
                const float* src = g_xg +
                    (size_t)((s + 1) * BB + b0 + bi) * G4 + g * HH + jg0 + (j4 << 2);
                uint32_t d = (uint32_t)__cvta_generic_to_shared(
                    &xg2[(((s + 1) & 1) << 10) + ((g << 4) + bi) * 16 + (j4 << 2)]);
                CP16(d, src);
                asm volatile("cp.async.commit_group;");
            }

            float C0[4] = {0.f, 0.f, 0.f, 0.f};
            float C1[4] = {0.f, 0.f, 0.f, 0.f};
            const __half* hr0 = hsu16 + gid * 520 + (kw << 7) + (tig << 1);
            const __half* hr1 = hsu16 + (gid + 8) * 520 + (kw << 7) + (tig << 1);
            #pragma unroll
            for (int kt = 0; kt < 8; kt++) {
                unsigned b0r = *(const unsigned*)(hr0 + (kt << 4));
                unsigned b1r = *(const unsigned*)(hr0 + (kt << 4) + 8);
                MMA_F16(C0, Ah[kt], b0r, b1r);
                unsigned b2r = *(const unsigned*)(hr1 + (kt << 4));
                unsigned b3r = *(const unsigned*)(hr1 + (kt << 4) + 8);
                MMA_F16(C1, Ah[kt], b2r, b3r);
            }

            // partials: red[(b*16+jl)*20 + kw*4+g]  (same C layout as tf32)
            {
                const int jlA = (mw << 2) + (gid >> 2);
                const int gA  = gid & 3;
                const int bA  = tig << 1;
                const int cA  = (kw << 2) + gA;
                red[((bA)     * 16 + jlA)     * 20 + cA] = C0[0];
                red[((bA + 1) * 16 + jlA)     * 20 + cA] = C0[1];
                red[((bA)     * 16 + jlA + 2) * 20 + cA] = C0[2];
                red[((bA + 1) * 16 + jlA + 2) * 20 + cA] = C0[3];
                red[((bA + 8) * 16 + jlA)     * 20 + cA] = C1[0];
                red[((bA + 9) * 16 + jlA)     * 20 + cA] = C1[1];
                red[((bA + 8) * 16 + jlA + 2) * 20 + cA] = C1[2];
                red[((bA + 9) * 16 + jlA + 2) * 20 + cA] = C1[3];
            }
        } else {
            // xg(0) must be resident (xg(1) may still be in flight)
            if (t < 256) asm volatile("cp.async.wait_group 1;");
        }
        __syncthreads();   // red ready; hsu reads complete

        if (t < 256) {
            // ---------------- owner phase (warps 0-7) ----------------
            const int jo = t & 15, bo = t >> 4;
            const float* xb = xg2 + ((s & 1) << 10);
            float a0 = xb[       (bo << 4) + jo];
            float a1 = xb[256 +  (bo << 4) + jo];
            float a2 = xb[512 +  (bo << 4) + jo];
            float a3 = xb[768 +  (bo << 4) + jo];
            if (s > 0) {
                const float4* rp = (const float4*)(red + t * 20);
                float4 q0 = rp[0], q1 = rp[1], q2 = rp[2], q3 = rp[3];
                a0 += q0.x + q1.x + q2.x + q3.x;
                a1 += q0.y + q1.y + q2.y + q3.y;
                a2 += q0.z + q1.z + q2.z + q3.z;
                a3 += q0.w + q1.w + q2.w + q3.w;
            }
            float ig = 1.f / (1.f + __expf(-a0));
            float fg = 1.f / (1.f + __expf(-a1));
            float gg = 2.f / (1.f + __expf(-2.f * a2)) - 1.f;
            float og = 1.f / (1.f + __expf(-a3));
            c = fg * c + ig * gg;
            float th = 2.f / (1.f + __expf(-2.f * c)) - 1.f;
            float h = og * th;
            // store h as fp16 (11-bit mantissa, same as tf32 rounding)
            g_hist16[((size_t)(s * BB + b0 + bo) << 9) + jg0 + jo] =
                __float2half_rn(h);

            // owners-only barrier, then release this step's counter
            asm volatile("bar.sync 9, 256;");
            if (t == 0)
                asm volatile("red.release.gpu.global.add.u32 [%0], %1;"
                             :: "l"(g_cnt + bgrp * SS + s), "r"(1u) : "memory");
        } else if (t == 256) {
            // overlapped producer poll (lane 0 of warp 8)
            const unsigned* ca = g_cnt + bgrp * SS + s;
            unsigned v;
            do {
                asm volatile("ld.acquire.gpu.global.u32 %0, [%1];"
                             : "=r"(v) : "l"(ca) : "memory");
            } while (v < NCTAG);
        }
        __syncthreads();   // owners released + producers verified -> next step
    }
}

extern "C" void kernel_launch(void* const* d_in, const int* in_sizes, int n_in,
                              void* d_out, int out_size)
{
    const float* inp  = (const float*)d_in[0];
    const float* Wih  = (const float*)d_in[1];
    const float* Whh  = (const float*)d_in[2];
    const float* bih  = (const float*)d_in[3];
    const float* bhh  = (const float*)d_in[4];
    const float* Wout = (const float*)d_in[5];
    const float* bout = (const float*)d_in[6];
    float* out = (float*)d_out;

    const int smem_bytes = SM_TOT * 4;    // 45,312 B
    const int xg_bytes   = XG_TOT * 4;    // 85,248 B
    cudaFuncSetAttribute(lstm_persist,
                         cudaFuncAttributeMaxDynamicSharedMemorySize, smem_bytes);
    cudaFuncSetAttribute(xg_tc,
                         cudaFuncAttributeMaxDynamicSharedMemorySize, xg_bytes);

    init_kernel<<<8, 256>>>();
    xg_tc<<<dim3(G4 / 64, 64), 256, xg_bytes>>>(inp, Wih, bih, bhh);
    lstm_persist<<<NCTA + NOUT, TPB, smem_bytes>>>(Whh, Wout, bout, out);
}

// round 17
// speedup vs baseline: 1.5703x; 1.0321x over previous
#include <cuda_runtime.h>
#include <cuda_fp16.h>
#include <math.h>
#include <stdint.h>

#define BB 64
#define SS 512
#define FF 128
#define HH 512
#define G4 2048
#define NCTA 128          // persist CTAs
#define NOUT 20           // out-role CTAs
#define NCTAG 32          // CTAs per b-group
#define TPB 512

// Scratch (static device globals — no allocation at kernel_launch time)
__device__ float g_xg[(size_t)SS * BB * G4];      // [S][B][4H] input gates (fp32)
__device__ __half g_hist16[(size_t)SS * BB * HH]; // [S][B][H] h in fp16
__device__ __half g_inp16[(size_t)BB * SS * FF];  // inputs converted to fp16
__device__ unsigned g_cnt[4 * SS];                // per-(bgroup,step) counters

#define CP16(dst, src) asm volatile("cp.async.cg.shared.global [%0], [%1], 16;" \
                                    :: "r"(dst), "l"(src))

#define MMA_F16(C, A, b0r, b1r) \
    asm volatile("mma.sync.aligned.m16n8k16.row.col.f32.f16.f16.f32 " \
        "{%0,%1,%2,%3}, {%4,%5,%6,%7}, {%8,%9}, {%0,%1,%2,%3};" \
        : "+f"(C[0]), "+f"(C[1]), "+f"(C[2]), "+f"(C[3]) \
        : "r"(A[0]), "r"(A[1]), "r"(A[2]), "r"(A[3]), "r"(b0r), "r"(b1r))

__device__ __forceinline__ unsigned packh2(float x, float y) {
    __half2 h = __floats2half2_rn(x, y);
    return *(unsigned*)&h;
}

// init: zero counters + convert inp to fp16 (layout preserved [B][S][F])
__global__ void init_kernel(const float* __restrict__ inp) {
    int i = blockIdx.x * blockDim.x + threadIdx.x;
    if (i < 4 * SS) g_cnt[i] = 0;
    const int n4 = (BB * SS * FF) >> 2;   // 1,048,576 float4 chunks
    if (i < n4) {
        float4 v = *(const float4*)(inp + ((size_t)i << 2));
        unsigned lo = packh2(v.x, v.y);
        unsigned hi = packh2(v.z, v.w);
        uint2 p = {lo, hi};
        *(uint2*)(g_inp16 + ((size_t)i << 2)) = p;
    }
}

// ---------------------------------------------------------------------------
// x_gates GEMM on tensor cores, now fp16 m16n8k16 (fp32 accum), double-
// buffered subtile pipeline.  C[g][m] = sum_f Wih[g,f]*inp[m,f]; out + bias.
// Grid (32 g-groups, 64 m-chunks).  CTA: 64 g x 512 m, 8 subtiles of 64 m.
// 8 warps = aw(4 g-tiles of 16) x nh(2 n-halves of 32).  A frags resident.
// SMEM: hsx16 2x(64x136 halves) = 8704 f | cs 64x68 f | bs 64 f
// ---------------------------------------------------------------------------
#define XG_CS  8704
#define XG_BS  13056
#define XG_TOT 13120

__global__ __launch_bounds__(256) void xg_tc(
    const float* __restrict__ Wih,
    const float* __restrict__ bih, const float* __restrict__ bhh)
{
    extern __shared__ float sx[];
    __half* hsx16 = (__half*)sx;             // two 8704-half buffers
    float* cs  = sx + XG_CS;
    float* bs  = sx + XG_BS;

    const int t = threadIdx.x;
    const int w = t >> 5, l = t & 31;
    const int gid = l >> 2, tig = l & 3;
    const int aw = w >> 1, nh = w & 1;
    const int gBase = blockIdx.x << 6;

    if (t < 64) bs[t] = bih[gBase + t] + bhh[gBase + t];

    // Resident A fragments (W_ih rows, fp16 pairs) — m16n8k16 layout
    unsigned Ah[8][4];
    {
        const int m0 = (aw << 4) + gid;
        const float* r0 = Wih + (size_t)(gBase + m0) * FF;
        const float* r1 = Wih + (size_t)(gBase + m0 + 8) * FF;
        #pragma unroll
        for (int kt = 0; kt < 8; kt++) {
            int kc = (kt << 4) + (tig << 1);
            Ah[kt][0] = packh2(__ldg(r0 + kc),     __ldg(r0 + kc + 1));
            Ah[kt][1] = packh2(__ldg(r1 + kc),     __ldg(r1 + kc + 1));
            Ah[kt][2] = packh2(__ldg(r0 + kc + 8), __ldg(r0 + kc + 9));
            Ah[kt][3] = packh2(__ldg(r1 + kc + 8), __ldg(r1 + kc + 9));
        }
    }

    // preload subtile 0 into buffer 0 (fp16: 16 KB, 4 CP16/thread)
    {
        const int sfix = (blockIdx.y << 3);
        #pragma unroll
        for (int it = 0; it < 4; it++) {
            int idx = t + (it << 8);
            int r = idx >> 4, c16 = idx & 15;
            uint32_t d = (uint32_t)__cvta_generic_to_shared(
                &hsx16[r * 136 + (c16 << 3)]);
            CP16(d, g_inp16 + ((size_t)r * SS + sfix) * FF + (c16 << 3));
        }
        asm volatile("cp.async.commit_group;");
    }

    for (int sub = 0; sub < 8; sub++) {
        const int sfix = (blockIdx.y << 3) + sub;

        if (sub < 7) {
            __half* dstb = hsx16 + (((sub + 1) & 1) * 8704);
            #pragma unroll
            for (int it = 0; it < 4; it++) {
                int idx = t + (it << 8);
                int r = idx >> 4, c16 = idx & 15;
                uint32_t d = (uint32_t)__cvta_generic_to_shared(
                    &dstb[r * 136 + (c16 << 3)]);
                CP16(d, g_inp16 + ((size_t)r * SS + sfix + 1) * FF + (c16 << 3));
            }
            asm volatile("cp.async.commit_group;");
            asm volatile("cp.async.wait_group 1;");
        } else {
            asm volatile("cp.async.wait_group 0;");
        }
        __syncthreads();

        const __half* buf = hsx16 + ((sub & 1) * 8704);

        float C[4][4] = {};
        #pragma unroll
        for (int nt = 0; nt < 4; nt++) {
            const __half* hb = buf + ((nh << 5) + (nt << 3) + gid) * 136 + (tig << 1);
            #pragma unroll
            for (int kt = 0; kt < 8; kt++) {
                unsigned b0r = *(const unsigned*)(hb + (kt << 4));
                unsigned b1r = *(const unsigned*)(hb + (kt << 4) + 8);
                MMA_F16(C[nt], Ah[kt], b0r, b1r);
            }
        }

        // stage C -> cs[mrow][g]  (same fragment layout as before)
        const int grow = (aw << 4) + gid;
        #pragma unroll
        for (int nt = 0; nt < 4; nt++) {
            int base = (nh << 5) + (nt << 3) + (tig << 1);
            cs[ base      * 68 + grow    ] = C[nt][0];
            cs[(base + 1) * 68 + grow    ] = C[nt][1];
            cs[ base      * 68 + grow + 8] = C[nt][2];
            cs[(base + 1) * 68 + grow + 8] = C[nt][3];
        }
        __syncthreads();

        // coalesced store with bias: 64 rows x 64 g
        #pragma unroll
        for (int it = 0; it < 4; it++) {
            int idx = t + (it << 8);
            int row = idx >> 4, c4 = idx & 15;
            float4 v = *(const float4*)&cs[row * 68 + (c4 << 2)];
            float4 bb = *(const float4*)&bs[c4 << 2];
            v.x += bb.x; v.y += bb.y; v.z += bb.z; v.w += bb.w;
            *(float4*)(g_xg + (size_t)((sfix << 6) + row) * G4 + gBase + (c4 << 2)) = v;
        }
        __syncthreads();
    }
}

// ---------------------------------------------------------------------------
// Fused persistent kernel, grid = 148 CTAs (R16, unchanged).
// Recurrent GEMM fp16 m16n8k16 (fp32 accum); h stored fp16 in g_hist16.
// Sync: per-b-group counter, red.release by t0 after owners' bar9; single
// poller (t==256) overlapped with the owner phase.
// SMEM (floats): hsu16 16x520 halves (4160 f) | xg2 2x1024 | red 256x20
// ---------------------------------------------------------------------------
#define SM_XG   4160
#define SM_RED  6208
#define SM_TOT  11328

__global__ __launch_bounds__(TPB, 1) void lstm_persist(
    const float* __restrict__ Whh, const float* __restrict__ Wout,
    const float* __restrict__ bout, float* __restrict__ out)
{
    extern __shared__ float sm[];
    const int t = threadIdx.x;

    if (blockIdx.x >= NCTA) {
        // ------------------- out-projection role -------------------
        float* As = sm;                 // [32][68]
        float* Bs = sm + 32 * 68;       // [32][68]
        const int o = blockIdx.x - NCTA;            // 0..19
        const int tx = t & 31, ty = t >> 5;         // f-pair, m-quad

        for (int tt = o; tt < 2 * SS; tt += NOUT) {
            const int s = tt >> 1;
            const int fBase = (tt & 1) << 6;

            // wait for all 4 b-groups of step s
            if (t < 4) {
                const unsigned* ca = g_cnt + t * SS + s;
                unsigned v;
                do {
                    asm volatile("ld.acquire.gpu.global.u32 %0, [%1];"
                                 : "=r"(v) : "l"(ca) : "memory");
                } while (v < NCTAG);
            }
            __syncthreads();

            float acc[4][2] = {};
            const __half* hb16 = g_hist16 + ((size_t)s << 15);

            for (int k0 = 0; k0 < HH; k0 += 32) {
                {   // h tile (fp16 -> fp32): 64 rows x 32 k
                    int row = t >> 3, c4 = t & 7;
                    const __half* src = hb16 + ((size_t)row << 9) + k0 + (c4 << 2);
                    __half2 p0 = *(const __half2*)(src);
                    __half2 p1 = *(const __half2*)(src + 2);
                    float2 f0 = __half22float2(p0);
                    float2 f1 = __half22float2(p1);
                    As[(c4 * 4 + 0) * 68 + row] = f0.x;
                    As[(c4 * 4 + 1) * 68 + row] = f0.y;
                    As[(c4 * 4 + 2) * 68 + row] = f1.x;
                    As[(c4 * 4 + 3) * 68 + row] = f1.y;
                }
                {
                    int row = t >> 3, c4 = t & 7;
                    float4 v = *(const float4*)(Wout +
                        (size_t)(fBase + row) * HH + k0 + (c4 << 2));
                    Bs[(c4 * 4 + 0) * 68 + row] = v.x;
                    Bs[(c4 * 4 + 1) * 68 + row] = v.y;
                    Bs[(c4 * 4 + 2) * 68 + row] = v.z;
                    Bs[(c4 * 4 + 3) * 68 + row] = v.w;
                }
                __syncthreads();
                #pragma unroll
                for (int kk = 0; kk < 32; kk++) {
                    float a[4], b[2];
                    *(float4*)a = *(const float4*)&As[kk * 68 + ty * 4];
                    b[0] = Bs[kk * 68 + tx * 2];
                    b[1] = Bs[kk * 68 + tx * 2 + 1];
                    #pragma unroll
                    for (int i = 0; i < 4; i++) {
                        acc[i][0] += a[i] * b[0];
                        acc[i][1] += a[i] * b[1];
                    }
                }
                __syncthreads();
            }

            float bias0 = bout[fBase + tx * 2];
            float bias1 = bout[fBase + tx * 2 + 1];
            #pragma unroll
            for (int i = 0; i < 4; i++) {
                int b = ty * 4 + i;
                float2 ov;
                ov.x = acc[i][0] + bias0;
                ov.y = acc[i][1] + bias1;
                *(float2*)(out + ((size_t)b * SS + s) * FF + fBase + tx * 2) = ov;
            }
        }
        return;
    }

    // ---------------------- LSTM persist role ----------------------
    __half* hsu16 = (__half*)sm;               // h tile fp16, pitch 520 halves
    float* xg2 = sm + SM_XG;
    float* red = sm + SM_RED;                  // [b*16+j][20]: kw*4+g

    const int w = t >> 5, l = t & 31;
    const int kw = w >> 2, mw = w & 3;         // k-split, m-split
    const int gid = l >> 2, tig = l & 3;       // mma lane decode
    const int jgrp = blockIdx.x >> 2;
    const int bgrp = blockIdx.x & 3;
    const int jg0  = jgrp << 4;
    const int b0   = bgrp << 4;

    // Resident A fragments (W_hh rows, fp16 pairs) — m16n8k16 layout
    unsigned Ah[8][4];
    {
        int m0 = (mw << 4) + gid;
        int m1 = m0 + 8;
        const float* r0 = Whh + (size_t)((m0 & 3) * HH + jg0 + (m0 >> 2)) * HH;
        const float* r1 = Whh + (size_t)((m1 & 3) * HH + jg0 + (m1 >> 2)) * HH;
        #pragma unroll
        for (int kt = 0; kt < 8; kt++) {
            int kc = (kw << 7) + (kt << 4) + (tig << 1);
            Ah[kt][0] = packh2(__ldg(r0 + kc),     __ldg(r0 + kc + 1));
            Ah[kt][1] = packh2(__ldg(r1 + kc),     __ldg(r1 + kc + 1));
            Ah[kt][2] = packh2(__ldg(r0 + kc + 8), __ldg(r0 + kc + 9));
            Ah[kt][3] = packh2(__ldg(r1 + kc + 8), __ldg(r1 + kc + 9));
        }
    }

    // Prefetch xg(0) and xg(1) (warps 0-7), separate commit groups
    if (t < 256) {
        int bi = t >> 4, cc = t & 15;
        int g = cc >> 2, j4 = cc & 3;
        {
            const float* src = g_xg + (size_t)(b0 + bi) * G4 + g * HH + jg0 + (j4 << 2);
            uint32_t d = (uint32_t)__cvta_generic_to_shared(
                &xg2[((g << 4) + bi) * 16 + (j4 << 2)]);
            CP16(d, src);
            asm volatile("cp.async.commit_group;");
        }
        {
            const float* src = g_xg + (size_t)(BB + b0 + bi) * G4 + g * HH + jg0 + (j4 << 2);
            uint32_t d = (uint32_t)__cvta_generic_to_shared(
                &xg2[1024 + ((g << 4) + bi) * 16 + (j4 << 2)]);
            CP16(d, src);
            asm volatile("cp.async.commit_group;");
        }
    }
    __syncthreads();

    float c = 0.f;

    for (int s = 0; s < SS; s++) {
        if (s > 0) {
            // h slice (fp16): warp (kw,mw) loads 16 rows x 32 halves (1 KB)
            {
                const __half* hp16 = g_hist16 + ((size_t)(s - 1) << 15);
                #pragma unroll
                for (int it = 0; it < 2; it++) {
                    int idx = (it << 5) + l;
                    int r = idx >> 2, cc8 = idx & 3;
                    int col = (kw << 7) + (mw << 5) + (cc8 << 3);
                    uint32_t d = (uint32_t)__cvta_generic_to_shared(
                        &hsu16[r * 520 + col]);
                    CP16(d, hp16 + ((size_t)(b0 + r) << 9) + col);
                }
                asm volatile("cp.async.commit_group;");
                asm volatile("cp.async.wait_group 0;");
                asm volatile("bar.sync %0, 128;" :: "r"(kw + 1));
            }

            // Prefetch xg(s+1) during compute (warps 0-7 only)
            if (t < 256 && s + 1 < SS) {
                int bi = t >> 4, cc = t & 15;
                int g = cc >> 2, j4 = cc & 3;
                const float* src = g_xg +
                    (size_t)((s + 1) * BB + b0 + bi) * G4 + g * HH + jg0 + (j4 << 2);
                uint32_t d = (uint32_t)__cvta_generic_to_shared(
                    &xg2[(((s + 1) & 1) << 10) + ((g << 4) + bi) * 16 + (j4 << 2)]);
                CP16(d, src);
                asm volatile("cp.async.commit_group;");
            }

            float C0[4] = {0.f, 0.f, 0.f, 0.f};
            float C1[4] = {0.f, 0.f, 0.f, 0.f};
            const __half* hr0 = hsu16 + gid * 520 + (kw << 7) + (tig << 1);
            const __half* hr1 = hsu16 + (gid + 8) * 520 + (kw << 7) + (tig << 1);
            #pragma unroll
            for (int kt = 0; kt < 8; kt++) {
                unsigned b0r = *(const unsigned*)(hr0 + (kt << 4));
                unsigned b1r = *(const unsigned*)(hr0 + (kt << 4) + 8);
                MMA_F16(C0, Ah[kt], b0r, b1r);
                unsigned b2r = *(const unsigned*)(hr1 + (kt << 4));
                unsigned b3r = *(const unsigned*)(hr1 + (kt << 4) + 8);
                MMA_F16(C1, Ah[kt], b2r, b3r);
            }

            // partials: red[(b*16+jl)*20 + kw*4+g]
            {
                const int jlA = (mw << 2) + (gid >> 2);
                const int gA  = gid & 3;
                const int bA  = tig << 1;
                const int cA  = (kw << 2) + gA;
                red[((bA)     * 16 + jlA)     * 20 + cA] = C0[0];
                red[((bA + 1) * 16 + jlA)     * 20 + cA] = C0[1];
                red[((bA)     * 16 + jlA + 2) * 20 + cA] = C0[2];
                red[((bA + 1) * 16 + jlA + 2) * 20 + cA] = C0[3];
                red[((bA + 8) * 16 + jlA)     * 20 + cA] = C1[0];
                red[((bA + 9) * 16 + jlA)     * 20 + cA] = C1[1];
                red[((bA + 8) * 16 + jlA + 2) * 20 + cA] = C1[2];
                red[((bA + 9) * 16 + jlA + 2) * 20 + cA] = C1[3];
            }
        } else {
            // xg(0) must be resident (xg(1) may still be in flight)
            if (t < 256) asm volatile("cp.async.wait_group 1;");
        }
        __syncthreads();   // red ready; hsu reads complete

        if (t < 256) {
            // ---------------- owner phase (warps 0-7) ----------------
            const int jo = t & 15, bo = t >> 4;
            const float* xb = xg2 + ((s & 1) << 10);
            float a0 = xb[       (bo << 4) + jo];
            float a1 = xb[256 +  (bo << 4) + jo];
            float a2 = xb[512 +  (bo << 4) + jo];
            float a3 = xb[768 +  (bo << 4) + jo];
            if (s > 0) {
                const float4* rp = (const float4*)(red + t * 20);
                float4 q0 = rp[0], q1 = rp[1], q2 = rp[2], q3 = rp[3];
                a0 += q0.x + q1.x + q2.x + q3.x;
                a1 += q0.y + q1.y + q2.y + q3.y;
                a2 += q0.z + q1.z + q2.z + q3.z;
                a3 += q0.w + q1.w + q2.w + q3.w;
            }
            float ig = 1.f / (1.f + __expf(-a0));
            float fg = 1.f / (1.f + __expf(-a1));
            float gg = 2.f / (1.f + __expf(-2.f * a2)) - 1.f;
            float og = 1.f / (1.f + __expf(-a3));
            c = fg * c + ig * gg;
            float th = 2.f / (1.f + __expf(-2.f * c)) - 1.f;
            float h = og * th;
            // store h as fp16 (11-bit mantissa, same as tf32 rounding)
            g_hist16[((size_t)(s * BB + b0 + bo) << 9) + jg0 + jo] =
                __float2half_rn(h);

            // owners-only barrier, then release this step's counter
            asm volatile("bar.sync 9, 256;");
            if (t == 0)
                asm volatile("red.release.gpu.global.add.u32 [%0], %1;"
                             :: "l"(g_cnt + bgrp * SS + s), "r"(1u) : "memory");
        } else if (t == 256) {
            // overlapped producer poll (lane 0 of warp 8)
            const unsigned* ca = g_cnt + bgrp * SS + s;
            unsigned v;
            do {
                asm volatile("ld.acquire.gpu.global.u32 %0, [%1];"
                             : "=r"(v) : "l"(ca) : "memory");
            } while (v < NCTAG);
        }
        __syncthreads();   // owners released + producers verified -> next step
    }
}

extern "C" void kernel_launch(void* const* d_in, const int* in_sizes, int n_in,
                              void* d_out, int out_size)
{
    const float* inp  = (const float*)d_in[0];
    const float* Wih  = (const float*)d_in[1];
    const float* Whh  = (const float*)d_in[2];
    const float* bih  = (const float*)d_in[3];
    const float* bhh  = (const float*)d_in[4];
    const float* Wout = (const float*)d_in[5];
    const float* bout = (const float*)d_in[6];
    float* out = (float*)d_out;

    const int smem_bytes = SM_TOT * 4;    // 45,312 B
    const int xg_bytes   = XG_TOT * 4;    // 52,480 B
    cudaFuncSetAttribute(lstm_persist,
                         cudaFuncAttributeMaxDynamicSharedMemorySize, smem_bytes);
    cudaFuncSetAttribute(xg_tc,
                         cudaFuncAttributeMaxDynamicSharedMemorySize, xg_bytes);

    init_kernel<<<4096, 256>>>(inp);
    xg_tc<<<dim3(G4 / 64, 64), 256, xg_bytes>>>(Wih, bih, bhh);
    lstm_persist<<<NCTA + NOUT, TPB, smem_bytes>>>(Whh, Wout, bout, out);
}